// round 4
// baseline (speedup 1.0000x reference)
#include <cuda_runtime.h>
#include <math.h>

#define VOCABN   10003
#define NITEMS   10000
#define PADTOK   10000
#define NPOS     512
#define SEQLEN   128
#define NTHREADS 256

__device__ int   g_seq[NPOS];
__device__ int   g_lab[NPOS];
__device__ float g_invpb[VOCABN];

// ---------------------------------------------------------------------------
// Pre-kernel: decode int64/int32 token arrays + compute 1/pop_biases
// ---------------------------------------------------------------------------
__global__ void pre_kernel(const void* __restrict__ seq_raw,
                           const void* __restrict__ lab_raw,
                           const float* __restrict__ pb)
{
    int v = blockIdx.x * NTHREADS + threadIdx.x;
    if (v < VOCABN) {
        float d = pb[v];
        g_invpb[v] = (d != 0.0f) ? (1.0f / d) : 0.0f;   // div_no_nan semantics
    }
    if (blockIdx.x == 0) {
        __shared__ int flag;
        if (threadIdx.x == 0) flag = 0;
        __syncthreads();
        const int* s32 = (const int*)seq_raw;
        const int* l32 = (const int*)lab_raw;
        // Probe only the first 256 elements' "high words": safe in both
        // interpretations (max index 511 < 512 elements of the narrowest case).
        for (int i = threadIdx.x; i < 256; i += NTHREADS) {
            int hs = s32[2 * i + 1];
            int hl = l32[2 * i + 1];
            if ((hs != 0 && hs != -1) || (hl != 0 && hl != -1)) atomicOr(&flag, 1);
        }
        __syncthreads();
        int is32 = flag;   // nonzero high words -> data is int32
        for (int i = threadIdx.x; i < NPOS; i += NTHREADS) {
            int idx = is32 ? i : 2 * i;    // single guarded index: no OOB either way
            g_seq[i] = s32[idx];
            g_lab[i] = l32[idx];
        }
    }
}

// ---------------------------------------------------------------------------
// Exact GELU via Abramowitz & Stegun 7.1.26 erf (|abs err| <= 1.5e-7)
// ---------------------------------------------------------------------------
__device__ __forceinline__ float gelu_exact(float z)
{
    float u  = z * 0.70710678118654752f;
    float au = fabsf(u);
    float t  = __fdividef(1.0f, fmaf(0.3275911f, au, 1.0f));
    float p  = fmaf(fmaf(fmaf(fmaf(1.061405429f, t, -1.453152027f),
                              t,  1.421413741f),
                         t, -0.284496736f),
                    t,  0.254829592f) * t;
    float e    = __expf(-au * au);
    float erfa = fmaf(-p, e, 1.0f);        // erf(|u|)
    float erfu = copysignf(erfa, u);
    float hz   = 0.5f * z;
    return fmaf(hz, erfu, hz);             // 0.5*z*(1+erf)
}

// ---------------------------------------------------------------------------
// Main kernel: one block per (b, t) position
// ---------------------------------------------------------------------------
__global__ __launch_bounds__(NTHREADS)
void bias_bert_kernel(const float* __restrict__ Tsrc,
                      const float* __restrict__ Tdst,
                      const float* __restrict__ pn,
                      const float* __restrict__ W1,
                      const float* __restrict__ b1,
                      const float* __restrict__ W2,
                      const float* __restrict__ b2,
                      float* __restrict__ out)
{
    __shared__ float slog[NITEMS];
    __shared__ float sw0[32], sw1[32], swr[32], sb1[32], sw2[32];
    __shared__ float swarp[8];
    __shared__ float sM;

    const int pos = blockIdx.x;
    const int b   = pos >> 7;          // pos / SEQLEN
    const int t   = pos & (SEQLEN - 1);
    const int tid = threadIdx.x;

    if (tid < 32) {
        sw0[tid] = W1[tid];            // W1[0][j]
        sw1[tid] = W1[32 + tid];       // W1[1][j]
        swr[tid] = W1[64 + tid];       // W1[2][j]
        sb1[tid] = b1[tid];
        sw2[tid] = W2[tid];
    }

    int src = (t == 0)          ? PADTOK : max(g_seq[b * SEQLEN + t - 1], 0);
    int dst = (t == SEQLEN - 1) ? PADTOK : max(g_seq[b * SEQLEN + t + 1], 0);
    int label = g_lab[pos];

    const float* rs = Tsrc + (size_t)src * VOCABN;
    const float* rd = Tdst + (size_t)dst * VOCABN;
    const float b2v = b2[0];

    __syncthreads();

    // ---- compute logits -------------------------------------------------
    for (int base = 0; base < NITEMS; base += NTHREADS * 8) {
        float x1[8], x2[8], x3[8], acc[8];
        #pragma unroll
        for (int k = 0; k < 8; k++) {
            int v = base + k * NTHREADS + tid;
            bool act = v < NITEMS;
            float ip = act ? g_invpb[v] : 0.0f;
            x1[k] = act ? rs[v] * ip : 0.0f;
            x2[k] = act ? rd[v] * ip : 0.0f;
            x3[k] = act ? pn[v]      : 0.0f;
            acc[k] = b2v;
        }
        #pragma unroll 4
        for (int j = 0; j < 32; j++) {
            float w0 = sw0[j], w1 = sw1[j], wr = swr[j], bb = sb1[j], w2 = sw2[j];
            #pragma unroll
            for (int k = 0; k < 8; k++) {
                float z = fmaf(x1[k], w0, fmaf(x2[k], w1, fmaf(x3[k], wr, bb)));
                float g = gelu_exact(z);
                acc[k] = fmaf(w2, g, acc[k]);
            }
        }
        #pragma unroll
        for (int k = 0; k < 8; k++) {
            int v = base + k * NTHREADS + tid;
            if (v < NITEMS) slog[v] = acc[k];
        }
    }
    __syncthreads();

    // ---- logsumexp: max -------------------------------------------------
    float m = -3.0e38f;
    for (int v = tid; v < NITEMS; v += NTHREADS) m = fmaxf(m, slog[v]);
    #pragma unroll
    for (int o = 16; o > 0; o >>= 1) m = fmaxf(m, __shfl_xor_sync(0xffffffffu, m, o));
    if ((tid & 31) == 0) swarp[tid >> 5] = m;
    __syncthreads();
    if (tid == 0) {
        float mm = swarp[0];
        #pragma unroll
        for (int i = 1; i < 8; i++) mm = fmaxf(mm, swarp[i]);
        sM = mm;
    }
    __syncthreads();
    const float M = sM;

    // ---- logsumexp: sum -------------------------------------------------
    float s = 0.0f;
    for (int v = tid; v < NITEMS; v += NTHREADS) s += __expf(slog[v] - M);
    #pragma unroll
    for (int o = 16; o > 0; o >>= 1) s += __shfl_xor_sync(0xffffffffu, s, o);
    __syncthreads();                      // protect swarp reuse
    if ((tid & 31) == 0) swarp[tid >> 5] = s;
    __syncthreads();

    if (tid == 0) {
        float ss = 0.0f;
        #pragma unroll
        for (int i = 0; i < 8; i++) ss += swarp[i];
        bool valid = (label != -100);
        int  li = min(max(label, 0), NITEMS - 1);
        float ce = logf(ss) + M - slog[li];
        out[pos] = valid ? ce : 0.0f;
    }
}

// ---------------------------------------------------------------------------
// Launch: inputs per metadata order
//  0 masked_sequences  1 labels  2 transitions_src  3 transitions_dst
//  4 pop_biases  5 pop_biases_norm  6 W1  7 b1  8 W2  9 b2
// ---------------------------------------------------------------------------
extern "C" void kernel_launch(void* const* d_in, const int* in_sizes, int n_in,
                              void* d_out, int out_size)
{
    const void*  seq  = d_in[0];
    const void*  lab  = d_in[1];
    const float* Tsrc = (const float*)d_in[2];
    const float* Tdst = (const float*)d_in[3];
    const float* pb   = (const float*)d_in[4];
    const float* pn   = (const float*)d_in[5];
    const float* W1   = (const float*)d_in[6];
    const float* b1   = (const float*)d_in[7];
    const float* W2   = (const float*)d_in[8];
    const float* b2   = (const float*)d_in[9];

    pre_kernel<<<(VOCABN + NTHREADS - 1) / NTHREADS, NTHREADS>>>(seq, lab, pb);
    bias_bert_kernel<<<NPOS, NTHREADS>>>(Tsrc, Tdst, pn, W1, b1, W2, b2,
                                         (float*)d_out);
}

// round 9
// speedup vs baseline: 2.2693x; 2.2693x over previous
#include <cuda_runtime.h>
#include <math.h>

#define VOCABN   10003
#define NITEMS   10000
#define PADTOK   10000
#define NPOS     512
#define SEQLEN   128
#define NTHREADS 256

__device__ int   g_seq[NPOS];
__device__ int   g_lab[NPOS];
__device__ float g_invpb[VOCABN];

// ---------------------------------------------------------------------------
// Pre-kernel: decode int64/int32 token arrays + compute 1/pop_biases
// ---------------------------------------------------------------------------
__global__ void pre_kernel(const void* __restrict__ seq_raw,
                           const void* __restrict__ lab_raw,
                           const float* __restrict__ pb)
{
    int v = blockIdx.x * NTHREADS + threadIdx.x;
    if (v < VOCABN) {
        float d = pb[v];
        g_invpb[v] = (d != 0.0f) ? (1.0f / d) : 0.0f;   // div_no_nan semantics
    }
    if (blockIdx.x == 0) {
        __shared__ int flag;
        if (threadIdx.x == 0) flag = 0;
        __syncthreads();
        const int* s32 = (const int*)seq_raw;
        const int* l32 = (const int*)lab_raw;
        // Probe first 256 elements' "high words": safe in both interpretations.
        for (int i = threadIdx.x; i < 256; i += NTHREADS) {
            int hs = s32[2 * i + 1];
            int hl = l32[2 * i + 1];
            if ((hs != 0 && hs != -1) || (hl != 0 && hl != -1)) atomicOr(&flag, 1);
        }
        __syncthreads();
        int is32 = flag;   // nonzero high words -> data is int32
        for (int i = threadIdx.x; i < NPOS; i += NTHREADS) {
            int idx = is32 ? i : 2 * i;
            g_seq[i] = s32[idx];
            g_lab[i] = l32[idx];
        }
    }
}

// ---------------------------------------------------------------------------
// Fast GELU: tanh form + HW tanh.approx.f32 (single MUFU op).
// gelu(z) = 0.5 z (1 + tanh(0.79788456 (z + 0.044715 z^3)))
// abs error vs exact-erf gelu ~3e-4 (formula) + ~5e-4 (HW tanh)  -> well
// inside the 1e-3 relative-error budget on the final CE (CE ~ 9.2).
// ---------------------------------------------------------------------------
__device__ __forceinline__ float tanh_fast(float x)
{
    float y;
    asm("tanh.approx.f32 %0, %1;" : "=f"(y) : "f"(x));
    return y;
}

__device__ __forceinline__ float gelu_fast(float z)
{
    float z2 = z * z;
    float w  = fmaf(0.0356774081f, z2, 0.7978845608f);  // 0.79788456*(1+0.044715 z^2)
    float th = tanh_fast(w * z);
    float hz = 0.5f * z;
    return fmaf(hz, th, hz);
}

// ---------------------------------------------------------------------------
// Main kernel: one block per (b, t) position
// ---------------------------------------------------------------------------
__global__ __launch_bounds__(NTHREADS)
void bias_bert_kernel(const float* __restrict__ Tsrc,
                      const float* __restrict__ Tdst,
                      const float* __restrict__ pn,
                      const float* __restrict__ W1,
                      const float* __restrict__ b1,
                      const float* __restrict__ W2,
                      const float* __restrict__ b2,
                      float* __restrict__ out)
{
    __shared__ float slog[NITEMS];
    __shared__ float sw0[32], sw1[32], swr[32], sb1[32], sw2[32];
    __shared__ float swarp[8];
    __shared__ float sM;

    const int pos = blockIdx.x;
    const int b   = pos >> 7;          // pos / SEQLEN
    const int t   = pos & (SEQLEN - 1);
    const int tid = threadIdx.x;

    if (tid < 32) {
        sw0[tid] = W1[tid];            // W1[0][j]
        sw1[tid] = W1[32 + tid];       // W1[1][j]
        swr[tid] = W1[64 + tid];       // W1[2][j]
        sb1[tid] = b1[tid];
        sw2[tid] = W2[tid];
    }

    int src = (t == 0)          ? PADTOK : max(g_seq[b * SEQLEN + t - 1], 0);
    int dst = (t == SEQLEN - 1) ? PADTOK : max(g_seq[b * SEQLEN + t + 1], 0);
    int label = g_lab[pos];

    const float* rs = Tsrc + (size_t)src * VOCABN;
    const float* rd = Tdst + (size_t)dst * VOCABN;
    const float b2v = b2[0];

    __syncthreads();

    // ---- compute logits -------------------------------------------------
    for (int base = 0; base < NITEMS; base += NTHREADS * 8) {
        float x1[8], x2[8], x3[8], acc[8];
        #pragma unroll
        for (int k = 0; k < 8; k++) {
            int v = base + k * NTHREADS + tid;
            bool act = v < NITEMS;
            float ip = act ? g_invpb[v] : 0.0f;
            x1[k] = act ? rs[v] * ip : 0.0f;
            x2[k] = act ? rd[v] * ip : 0.0f;
            x3[k] = act ? pn[v]      : 0.0f;
            acc[k] = b2v;
        }
        #pragma unroll 4
        for (int j = 0; j < 32; j++) {
            float w0 = sw0[j], w1 = sw1[j], wr = swr[j], bb = sb1[j], w2 = sw2[j];
            #pragma unroll
            for (int k = 0; k < 8; k++) {
                float z = fmaf(x1[k], w0, fmaf(x2[k], w1, fmaf(x3[k], wr, bb)));
                float g = gelu_fast(z);
                acc[k] = fmaf(w2, g, acc[k]);
            }
        }
        #pragma unroll
        for (int k = 0; k < 8; k++) {
            int v = base + k * NTHREADS + tid;
            if (v < NITEMS) slog[v] = acc[k];
        }
    }
    __syncthreads();

    // ---- logsumexp: max -------------------------------------------------
    float m = -3.0e38f;
    for (int v = tid; v < NITEMS; v += NTHREADS) m = fmaxf(m, slog[v]);
    #pragma unroll
    for (int o = 16; o > 0; o >>= 1) m = fmaxf(m, __shfl_xor_sync(0xffffffffu, m, o));
    if ((tid & 31) == 0) swarp[tid >> 5] = m;
    __syncthreads();
    if (tid == 0) {
        float mm = swarp[0];
        #pragma unroll
        for (int i = 1; i < 8; i++) mm = fmaxf(mm, swarp[i]);
        sM = mm;
    }
    __syncthreads();
    const float M = sM;

    // ---- logsumexp: sum -------------------------------------------------
    float s = 0.0f;
    for (int v = tid; v < NITEMS; v += NTHREADS) s += __expf(slog[v] - M);
    #pragma unroll
    for (int o = 16; o > 0; o >>= 1) s += __shfl_xor_sync(0xffffffffu, s, o);
    __syncthreads();                      // protect swarp reuse
    if ((tid & 31) == 0) swarp[tid >> 5] = s;
    __syncthreads();

    if (tid == 0) {
        float ss = 0.0f;
        #pragma unroll
        for (int i = 0; i < 8; i++) ss += swarp[i];
        bool valid = (label != -100);
        int  li = min(max(label, 0), NITEMS - 1);
        float ce = logf(ss) + M - slog[li];
        out[pos] = valid ? ce : 0.0f;
    }
}

// ---------------------------------------------------------------------------
// Launch: inputs per metadata order
//  0 masked_sequences  1 labels  2 transitions_src  3 transitions_dst
//  4 pop_biases  5 pop_biases_norm  6 W1  7 b1  8 W2  9 b2
// ---------------------------------------------------------------------------
extern "C" void kernel_launch(void* const* d_in, const int* in_sizes, int n_in,
                              void* d_out, int out_size)
{
    const void*  seq  = d_in[0];
    const void*  lab  = d_in[1];
    const float* Tsrc = (const float*)d_in[2];
    const float* Tdst = (const float*)d_in[3];
    const float* pb   = (const float*)d_in[4];
    const float* pn   = (const float*)d_in[5];
    const float* W1   = (const float*)d_in[6];
    const float* b1   = (const float*)d_in[7];
    const float* W2   = (const float*)d_in[8];
    const float* b2   = (const float*)d_in[9];

    pre_kernel<<<(VOCABN + NTHREADS - 1) / NTHREADS, NTHREADS>>>(seq, lab, pb);
    bias_bert_kernel<<<NPOS, NTHREADS>>>(Tsrc, Tdst, pn, W1, b1, W2, b2,
                                         (float*)d_out);
}

// round 10
// speedup vs baseline: 2.5968x; 1.1443x over previous
#include <cuda_runtime.h>
#include <math.h>

#define VOCABN   10003
#define NITEMS   10000
#define PADTOK   10000
#define NPOS     512
#define SEQLEN   128
#define NTHREADS 256

typedef unsigned long long u64;

__device__ int   g_seq[NPOS];
__device__ int   g_lab[NPOS];
__device__ float g_invpb[VOCABN];

// ---------------------------------------------------------------------------
// f32x2 packed-math helpers (Blackwell; ptxas never auto-fuses these)
// ---------------------------------------------------------------------------
#define FMA2(d, a, b, c) \
    asm("fma.rn.f32x2 %0, %1, %2, %3;" : "=l"(d) : "l"(a), "l"(b), "l"(c))
#define MUL2(d, a, b) \
    asm("mul.rn.f32x2 %0, %1, %2;" : "=l"(d) : "l"(a), "l"(b))
#define PACK2(d, lo, hi) \
    asm("mov.b64 %0, {%1, %2};" : "=l"(d) : "f"(lo), "f"(hi))
#define UNPACK2(lo, hi, d) \
    asm("mov.b64 {%0, %1}, %2;" : "=f"(lo), "=f"(hi) : "l"(d))

__device__ __forceinline__ float tanh_fast(float x)
{
    float y;
    asm("tanh.approx.f32 %0, %1;" : "=f"(y) : "f"(x));
    return y;
}

// ---------------------------------------------------------------------------
// Pre-kernel: decode int64/int32 token arrays + compute 1/pop_biases
// ---------------------------------------------------------------------------
__global__ void pre_kernel(const void* __restrict__ seq_raw,
                           const void* __restrict__ lab_raw,
                           const float* __restrict__ pb)
{
    int v = blockIdx.x * NTHREADS + threadIdx.x;
    if (v < VOCABN) {
        float d = pb[v];
        g_invpb[v] = (d != 0.0f) ? (1.0f / d) : 0.0f;   // div_no_nan semantics
    }
    if (blockIdx.x == 0) {
        __shared__ int flag;
        if (threadIdx.x == 0) flag = 0;
        __syncthreads();
        const int* s32 = (const int*)seq_raw;
        const int* l32 = (const int*)lab_raw;
        for (int i = threadIdx.x; i < 256; i += NTHREADS) {
            int hs = s32[2 * i + 1];
            int hl = l32[2 * i + 1];
            if ((hs != 0 && hs != -1) || (hl != 0 && hl != -1)) atomicOr(&flag, 1);
        }
        __syncthreads();
        int is32 = flag;   // nonzero high words -> data is int32
        for (int i = threadIdx.x; i < NPOS; i += NTHREADS) {
            int idx = is32 ? i : 2 * i;
            g_seq[i] = s32[idx];
            g_lab[i] = l32[idx];
        }
    }
}

// ---------------------------------------------------------------------------
// Main kernel: one block per (b, t) position.
// Logit MLP vectorized 2-wide with fma.rn.f32x2; tanh stays scalar MUFU.
//   logit = b2 + sum_j (0.5*w2_j) * (z*tanh(c(z)) + z),  z = x.W1_j + b1_j
// ---------------------------------------------------------------------------
__global__ __launch_bounds__(NTHREADS, 4)
void bias_bert_kernel(const float* __restrict__ Tsrc,
                      const float* __restrict__ Tdst,
                      const float* __restrict__ pn,
                      const float* __restrict__ W1,
                      const float* __restrict__ b1,
                      const float* __restrict__ W2,
                      const float* __restrict__ b2,
                      float* __restrict__ out)
{
    __shared__ float  slog[NITEMS];
    __shared__ float2 sw0[32], sw1[32], swr[32], sb1[32], sw2h[32];
    __shared__ float  swarp[8];
    __shared__ float  sM;

    const int pos = blockIdx.x;
    const int b   = pos >> 7;
    const int t   = pos & (SEQLEN - 1);
    const int tid = threadIdx.x;

    if (tid < 32) {
        float a0 = W1[tid];         sw0[tid]  = make_float2(a0, a0);
        float a1 = W1[32 + tid];    sw1[tid]  = make_float2(a1, a1);
        float ar = W1[64 + tid];    swr[tid]  = make_float2(ar, ar);
        float ab = b1[tid];         sb1[tid]  = make_float2(ab, ab);
        float a2 = 0.5f * W2[tid];  sw2h[tid] = make_float2(a2, a2);  // fold 0.5
    }

    int src = (t == 0)          ? PADTOK : max(g_seq[b * SEQLEN + t - 1], 0);
    int dst = (t == SEQLEN - 1) ? PADTOK : max(g_seq[b * SEQLEN + t + 1], 0);
    int label = g_lab[pos];

    const float* rs = Tsrc + (size_t)src * VOCABN;
    const float* rd = Tdst + (size_t)dst * VOCABN;
    const float b2v = b2[0];

    // packed tanh-gelu constants
    u64 C_A, C_B;
    PACK2(C_A, 0.0356774081f, 0.0356774081f);
    PACK2(C_B, 0.7978845608f, 0.7978845608f);

    __syncthreads();

    // ---- compute logits: 4 packed pairs (8 vocab entries) per thread ----
    for (int base = 0; base < NITEMS; base += NTHREADS * 8) {
        u64 x1p[4], x2p[4], x3p[4], accp[4];
        #pragma unroll
        for (int p = 0; p < 4; p++) {
            int v0 = base + (2 * p)     * NTHREADS + tid;
            int v1 = base + (2 * p + 1) * NTHREADS + tid;
            bool a0 = v0 < NITEMS, a1 = v1 < NITEMS;
            float ip0 = a0 ? g_invpb[v0] : 0.0f;
            float ip1 = a1 ? g_invpb[v1] : 0.0f;
            float s0 = a0 ? rs[v0] * ip0 : 0.0f;
            float s1 = a1 ? rs[v1] * ip1 : 0.0f;
            float d0 = a0 ? rd[v0] * ip0 : 0.0f;
            float d1 = a1 ? rd[v1] * ip1 : 0.0f;
            float p0 = a0 ? pn[v0] : 0.0f;
            float p1 = a1 ? pn[v1] : 0.0f;
            PACK2(x1p[p], s0, s1);
            PACK2(x2p[p], d0, d1);
            PACK2(x3p[p], p0, p1);
            PACK2(accp[p], b2v, b2v);
        }
        #pragma unroll 4
        for (int j = 0; j < 32; j++) {
            u64 w0  = *(const u64*)&sw0[j];
            u64 w1  = *(const u64*)&sw1[j];
            u64 wr  = *(const u64*)&swr[j];
            u64 bb  = *(const u64*)&sb1[j];
            u64 w2h = *(const u64*)&sw2h[j];
            #pragma unroll
            for (int p = 0; p < 4; p++) {
                u64 z, z2, w, wz, th, o;
                FMA2(z, x3p[p], wr, bb);
                FMA2(z, x2p[p], w1, z);
                FMA2(z, x1p[p], w0, z);
                MUL2(z2, z, z);
                FMA2(w, C_A, z2, C_B);
                MUL2(wz, w, z);
                float wl, wh;
                UNPACK2(wl, wh, wz);
                float tl = tanh_fast(wl);
                float thh = tanh_fast(wh);
                PACK2(th, tl, thh);
                FMA2(o, z, th, z);            // z*tanh + z  (= 2*gelu(z))
                FMA2(accp[p], w2h, o, accp[p]);
            }
        }
        #pragma unroll
        for (int p = 0; p < 4; p++) {
            int v0 = base + (2 * p)     * NTHREADS + tid;
            int v1 = base + (2 * p + 1) * NTHREADS + tid;
            float l0, l1;
            UNPACK2(l0, l1, accp[p]);
            if (v0 < NITEMS) slog[v0] = l0;
            if (v1 < NITEMS) slog[v1] = l1;
        }
    }
    __syncthreads();

    // ---- logsumexp: max -------------------------------------------------
    float m = -3.0e38f;
    for (int v = tid; v < NITEMS; v += NTHREADS) m = fmaxf(m, slog[v]);
    #pragma unroll
    for (int o = 16; o > 0; o >>= 1) m = fmaxf(m, __shfl_xor_sync(0xffffffffu, m, o));
    if ((tid & 31) == 0) swarp[tid >> 5] = m;
    __syncthreads();
    if (tid == 0) {
        float mm = swarp[0];
        #pragma unroll
        for (int i = 1; i < 8; i++) mm = fmaxf(mm, swarp[i]);
        sM = mm;
    }
    __syncthreads();
    const float M = sM;

    // ---- logsumexp: sum -------------------------------------------------
    float s = 0.0f;
    for (int v = tid; v < NITEMS; v += NTHREADS) s += __expf(slog[v] - M);
    #pragma unroll
    for (int o = 16; o > 0; o >>= 1) s += __shfl_xor_sync(0xffffffffu, s, o);
    __syncthreads();
    if ((tid & 31) == 0) swarp[tid >> 5] = s;
    __syncthreads();

    if (tid == 0) {
        float ss = 0.0f;
        #pragma unroll
        for (int i = 0; i < 8; i++) ss += swarp[i];
        bool valid = (label != -100);
        int  li = min(max(label, 0), NITEMS - 1);
        float ce = logf(ss) + M - slog[li];
        out[pos] = valid ? ce : 0.0f;
    }
}

// ---------------------------------------------------------------------------
// Launch: inputs per metadata order
//  0 masked_sequences  1 labels  2 transitions_src  3 transitions_dst
//  4 pop_biases  5 pop_biases_norm  6 W1  7 b1  8 W2  9 b2
// ---------------------------------------------------------------------------
extern "C" void kernel_launch(void* const* d_in, const int* in_sizes, int n_in,
                              void* d_out, int out_size)
{
    const void*  seq  = d_in[0];
    const void*  lab  = d_in[1];
    const float* Tsrc = (const float*)d_in[2];
    const float* Tdst = (const float*)d_in[3];
    const float* pb   = (const float*)d_in[4];
    const float* pn   = (const float*)d_in[5];
    const float* W1   = (const float*)d_in[6];
    const float* b1   = (const float*)d_in[7];
    const float* W2   = (const float*)d_in[8];
    const float* b2   = (const float*)d_in[9];

    pre_kernel<<<(VOCABN + NTHREADS - 1) / NTHREADS, NTHREADS>>>(seq, lab, pb);
    bias_bert_kernel<<<NPOS, NTHREADS>>>(Tsrc, Tdst, pn, W1, b1, W2, b2,
                                         (float*)d_out);
}